// round 14
// baseline (speedup 1.0000x reference)
#include <cuda_runtime.h>
#include <cuda_fp16.h>
#include <cstdint>

// LinearAttention n=4, L=8192, h=8, d=m=64 — f16 mma.sync m16n8k16 + ldmatrix.
// kv: cp.async operand delivery (R13-proven) + fused last-CTA-per-pair reduction.
// out[pair,l,m] = z_l * sum_d phiQ[l,d] * KV[d,m]
// KV[d,m] = sum_s phiK[s,d] V[s,m];  z_l = 1/(phiQ[l,:]·ksum + 1e-6)

#define NB 4
#define LL 8192
#define NH 8
#define DD 64
#define NPAIR 32
#define SPL 32
#define CHUNK (LL / SPL)       // 256
#define ROWS 32
#define NRND (CHUNK / ROWS)    // 8
#define TLQ 64
#define NT  4
#define PH  72                 // f16 pitch in halves (144 B)
#define PHB (PH * 2)
#define RPF 68                 // raw fp32 pitch in floats (272 B)

// kv smem layout (dynamic)
#define KRAW_OFF 0
#define VRAW_OFF (2 * ROWS * RPF * 4)                  // 17408
#define KS_OFF   (VRAW_OFF + 2 * ROWS * RPF * 4)       // 34816
#define VS_OFF   (KS_OFF + 2 * ROWS * PHB)             // 44032
#define KSUM_OFF (VS_OFF + 2 * ROWS * PHB)             // 53248
#define K1_SMEM  (KSUM_OFF + DD * 4)                   // 53504
#define SBUF     (ROWS * PHB)                          // 4608

__device__ float  g_kv_part[SPL * NPAIR * DD * DD];
__device__ float  g_ksum_part[SPL * NPAIR * DD];
__device__ __half g_kvh[NPAIR * DD * DD];
__device__ float  g_ksum[NPAIR * DD];
__device__ int    g_cnt[NPAIR];     // zero-initialized; reset by reducer each launch

// ---------------- helpers ----------------
__device__ __forceinline__ uint32_t s2u(const void* p) {
    uint32_t a;
    asm("{ .reg .u64 t; cvta.to.shared.u64 t, %1; cvt.u32.u64 %0, t; }" : "=r"(a) : "l"(p));
    return a;
}
__device__ __forceinline__ float phi(float x) {
    x *= 0.35355339059327378f;            // 64^-0.25
    return x > 0.f ? x + 1.f : __expf(x);
}
__device__ __forceinline__ uint32_t packh2(float lo, float hi) {
    __half2 h = __floats2half2_rn(lo, hi);
    return *reinterpret_cast<uint32_t*>(&h);
}
__device__ __forceinline__ void mma16(float c[4], uint32_t a0, uint32_t a1,
                                      uint32_t a2, uint32_t a3,
                                      uint32_t b0, uint32_t b1) {
    asm volatile(
        "mma.sync.aligned.m16n8k16.row.col.f32.f16.f16.f32 "
        "{%0,%1,%2,%3}, {%4,%5,%6,%7}, {%8,%9}, {%0,%1,%2,%3};"
        : "+f"(c[0]), "+f"(c[1]), "+f"(c[2]), "+f"(c[3])
        : "r"(a0), "r"(a1), "r"(a2), "r"(a3), "r"(b0), "r"(b1));
}
#define LDSM_X4(r0, r1, r2, r3, addr) \
    asm volatile("ldmatrix.sync.aligned.m8n8.x4.shared.b16 {%0,%1,%2,%3}, [%4];" \
                 : "=r"(r0), "=r"(r1), "=r"(r2), "=r"(r3) : "r"(addr))
#define LDSM_X4T(r0, r1, r2, r3, addr) \
    asm volatile("ldmatrix.sync.aligned.m8n8.x4.trans.shared.b16 {%0,%1,%2,%3}, [%4];" \
                 : "=r"(r0), "=r"(r1), "=r"(r2), "=r"(r3) : "r"(addr))
__device__ __forceinline__ void cp16(uint32_t dst, const void* src) {
    asm volatile("cp.async.cg.shared.global [%0], [%1], 16;"
                 :: "r"(dst), "l"(src) : "memory");
}
#define CP_COMMIT() asm volatile("cp.async.commit_group;" ::: "memory")
#define CP_WAIT(N)  asm volatile("cp.async.wait_group %0;" :: "n"(N) : "memory")

// ---------------- kernel 1: KV partials + fused reduction ----------------
__global__ __launch_bounds__(256)
void kv_kernel(const float* __restrict__ K, const float* __restrict__ V) {
    extern __shared__ char sm1[];
    const uint32_t smb = s2u(sm1);
    float* ksum_s = (float*)(sm1 + KSUM_OFF);
    __shared__ int s_last;

    const int tid = threadIdx.x, warp = tid >> 5, lane = tid & 31;
    const int gid = lane >> 2, tig = lane & 3;
    const int pair = blockIdx.y, b = pair >> 3, hh = pair & 7;
    const int split = blockIdx.x;
    const int wd = warp & 3, wm = warp >> 2;
    const int d0 = wd * 16, m0 = wm * 32;

    const size_t rstr = (size_t)NH * DD;
    const int lrow = tid >> 3, lcol = (tid & 7) * 8;
    const float* Kp = K + ((size_t)b * LL + split * CHUNK + lrow) * rstr + hh * DD + lcol;
    const float* Vp = V + ((size_t)b * LL + split * CHUNK + lrow) * rstr + hh * DD + lcol;

    const uint32_t krd = smb + KRAW_OFF + ((uint32_t)lrow * RPF + lcol) * 4;
    const uint32_t vrd = smb + VRAW_OFF + ((uint32_t)lrow * RPF + lcol) * 4;
    const uint32_t rawB = ROWS * RPF * 4;
    const uint32_t ksd = smb + KS_OFF + (uint32_t)lrow * PHB + lcol * 2;
    const uint32_t vsd = smb + VS_OFF + (uint32_t)lrow * PHB + lcol * 2;

    if (tid < DD) ksum_s[tid] = 0.f;

    float acc[4][4];
    #pragma unroll
    for (int i = 0; i < 4; i++)
        #pragma unroll
        for (int j = 0; j < 4; j++) acc[i][j] = 0.f;
    float ks[8];
    #pragma unroll
    for (int j = 0; j < 8; j++) ks[j] = 0.f;

    const int lr8  = lane & 7;
    const int sel3 = (lane >> 3) & 1;
    const int sel4 = (lane >> 4) & 1;
    const uint32_t a_addr0 = smb + KS_OFF + (uint32_t)(lr8 + sel4 * 8) * PHB
                                          + (uint32_t)(d0 + sel3 * 8) * 2;
    const uint32_t b_addr0 = smb + VS_OFF + (uint32_t)(lr8 + sel3 * 8) * PHB
                                          + (uint32_t)(m0 + sel4 * 8) * 2;

    cp16(krd, Kp); cp16(krd + 16, Kp + 4);
    cp16(vrd, Vp); cp16(vrd + 16, Vp + 4);
    CP_COMMIT();

    #pragma unroll
    for (int r = 0; r < NRND; r++) {
        const int buf = r & 1;
        if (r + 1 < NRND) {
            const size_t go = (size_t)(r + 1) * ROWS * rstr;
            const uint32_t so = (uint32_t)((r + 1) & 1) * rawB;
            cp16(krd + so, Kp + go); cp16(krd + so + 16, Kp + go + 4);
            cp16(vrd + so, Vp + go); cp16(vrd + so + 16, Vp + go + 4);
            CP_COMMIT();
            CP_WAIT(1);
        } else {
            CP_WAIT(0);
        }
        {
            const char* krp = sm1 + KRAW_OFF + buf * rawB + ((uint32_t)lrow * RPF + lcol) * 4;
            const char* vrp = sm1 + VRAW_OFF + buf * rawB + ((uint32_t)lrow * RPF + lcol) * 4;
            float4 ka = *(const float4*)krp;
            float4 kb = *(const float4*)(krp + 16);
            float4 va = *(const float4*)vrp;
            float4 vb = *(const float4*)(vrp + 16);
            float p[8];
            p[0] = phi(ka.x); p[1] = phi(ka.y); p[2] = phi(ka.z); p[3] = phi(ka.w);
            p[4] = phi(kb.x); p[5] = phi(kb.y); p[6] = phi(kb.z); p[7] = phi(kb.w);
            #pragma unroll
            for (int j = 0; j < 8; j++) ks[j] += p[j];
            uint4 hk = make_uint4(packh2(p[0], p[1]), packh2(p[2], p[3]),
                                  packh2(p[4], p[5]), packh2(p[6], p[7]));
            uint4 hv = make_uint4(packh2(va.x, va.y), packh2(va.z, va.w),
                                  packh2(vb.x, vb.y), packh2(vb.z, vb.w));
            asm volatile("st.shared.v4.b32 [%0], {%1,%2,%3,%4};"
                         :: "r"(ksd + buf * SBUF), "r"(hk.x), "r"(hk.y), "r"(hk.z), "r"(hk.w));
            asm volatile("st.shared.v4.b32 [%0], {%1,%2,%3,%4};"
                         :: "r"(vsd + buf * SBUF), "r"(hv.x), "r"(hv.y), "r"(hv.z), "r"(hv.w));
        }
        __syncthreads();

        const uint32_t aB = a_addr0 + buf * SBUF;
        const uint32_t bB = b_addr0 + buf * SBUF;
        #pragma unroll
        for (int kk = 0; kk < 2; kk++) {
            uint32_t a0, a1, a2, a3;
            LDSM_X4T(a0, a1, a2, a3, aB + (uint32_t)(kk * 16) * PHB);
            #pragma unroll
            for (int ntp = 0; ntp < 2; ntp++) {
                uint32_t b0, b1, b2, b3;
                LDSM_X4T(b0, b1, b2, b3,
                         bB + (uint32_t)(kk * 16) * PHB + (uint32_t)(ntp * 16) * 2);
                mma16(acc[ntp * 2],     a0, a1, a2, a3, b0, b1);
                mma16(acc[ntp * 2 + 1], a0, a1, a2, a3, b2, b3);
            }
        }
    }

    // ---- partial KV -> gmem ----
    float* dst = g_kv_part + ((size_t)split * NPAIR + pair) * DD * DD;
    const int dlo = d0 + gid;
    #pragma unroll
    for (int nt = 0; nt < 4; nt++) {
        const int m = m0 + nt * 8 + 2 * tig;
        *(float2*)(dst + dlo * DD + m)       = make_float2(acc[nt][0], acc[nt][1]);
        *(float2*)(dst + (dlo + 8) * DD + m) = make_float2(acc[nt][2], acc[nt][3]);
    }
    #pragma unroll
    for (int j = 0; j < 8; j++) {
        ks[j] += __shfl_xor_sync(0xffffffffu, ks[j], 8);
        ks[j] += __shfl_xor_sync(0xffffffffu, ks[j], 16);
    }
    __syncthreads();
    if (lane < 8) {
        #pragma unroll
        for (int j = 0; j < 8; j++)
            atomicAdd(&ksum_s[lane * 8 + j], ks[j]);
    }
    __syncthreads();
    if (tid < DD)
        g_ksum_part[((size_t)split * NPAIR + pair) * DD + tid] = ksum_s[tid];

    // ---- fused reduction: last CTA of this pair sums all 32 partials ----
    __threadfence();
    __syncthreads();
    if (tid == 0) {
        const int old = atomicAdd(&g_cnt[pair], 1);
        s_last = (old == SPL - 1) ? 1 : 0;
    }
    __syncthreads();
    if (s_last) {
        const size_t base = (size_t)pair * DD * DD;
        #pragma unroll
        for (int it = 0; it < (DD * DD) / (256 * 4); it++) {
            const int i = (it * 256 + tid) * 4;
            float4 s = make_float4(0.f, 0.f, 0.f, 0.f);
            #pragma unroll
            for (int p = 0; p < SPL; p++) {
                const float4 v = *(const float4*)(g_kv_part
                                    + (size_t)p * NPAIR * DD * DD + base + i);
                s.x += v.x; s.y += v.y; s.z += v.z; s.w += v.w;
            }
            __half2* d2 = (__half2*)(g_kvh + base + i);
            d2[0] = __floats2half2_rn(s.x, s.y);
            d2[1] = __floats2half2_rn(s.z, s.w);
        }
        if (tid < DD) {
            float s = 0.f;
            #pragma unroll
            for (int p = 0; p < SPL; p++)
                s += g_ksum_part[p * NPAIR * DD + pair * DD + tid];
            g_ksum[pair * DD + tid] = s;
        }
        __syncthreads();
        if (tid == 0) g_cnt[pair] = 0;   // reset for next graph replay
    }
}

// ---------------- kernel 2: output GEMM (R11-proven f16 + ldmatrix) --------
#define QS_BYTES  (2 * TLQ * PH * 2)
#define KVS_BYTES (DD * PH * 2)
#define K2_SMEM   (QS_BYTES + KVS_BYTES + 2 * TLQ * 4)

__global__ __launch_bounds__(256)
void out_kernel(const float* __restrict__ Q, float* __restrict__ O) {
    extern __shared__ char smx[];
    const uint32_t smb = s2u(smx);
    float* zsb = (float*)(smx + QS_BYTES + KVS_BYTES);

    const int tid = threadIdx.x, warp = tid >> 5, lane = tid & 31;
    const int gid = lane >> 2, tig = lane & 3;
    const int pair = blockIdx.y, b = pair >> 3, hh = pair & 7;
    const int lbase = blockIdx.x * (TLQ * NT);

    {
        const int krow = tid >> 2, kck = tid & 3;
        const __half* src = g_kvh + (size_t)pair * DD * DD + krow * DD + kck * 16;
        const uint32_t dst = smb + QS_BYTES + (uint32_t)krow * PHB + kck * 32;
        cp16(dst, src); cp16(dst + 16, src + 8);
    }
    CP_COMMIT();

    const int row = tid >> 2, qtr = tid & 3;
    const float* ksg = g_ksum + pair * DD + qtr * 16;
    float4 k4[4];
    #pragma unroll
    for (int i = 0; i < 4; i++) k4[i] = __ldg((const float4*)(ksg + i * 4));

    const float* qbase = Q + ((size_t)b * LL + lbase + row) * (NH * DD)
                           + (size_t)hh * DD + qtr * 16;
    float4 qv[4];
    #pragma unroll
    for (int i = 0; i < 4; i++) qv[i] = *(const float4*)(qbase + i * 4);

    const int lw = (warp & 3) * 16;
    const int m0w = (warp >> 2) * 32;

    const int lr8  = lane & 7;
    const int seld = (lane >> 3) & 1;
    const int selc = (lane >> 4) & 1;
    const uint32_t a_row_bytes = (uint32_t)(lw + lr8 + seld * 8) * PHB;
    const uint32_t b_base = smb + QS_BYTES
                          + (uint32_t)(lr8 + seld * 8) * PHB
                          + (uint32_t)(m0w + selc * 8) * 2;

    #pragma unroll
    for (int t = 0; t < NT; t++) {
        const int buf = t & 1;
        const uint32_t qs_off = (uint32_t)buf * (TLQ * PHB);
        float* zs = zsb + buf * TLQ;

        {
            float accz = 0.f;
            uint32_t h[8];
            #pragma unroll
            for (int i = 0; i < 4; i++) {
                float4 q4 = qv[i];
                q4.x = phi(q4.x); q4.y = phi(q4.y); q4.z = phi(q4.z); q4.w = phi(q4.w);
                accz += q4.x * k4[i].x + q4.y * k4[i].y
                      + q4.z * k4[i].z + q4.w * k4[i].w;
                h[i * 2]     = packh2(q4.x, q4.y);
                h[i * 2 + 1] = packh2(q4.z, q4.w);
            }
            accz += __shfl_xor_sync(0xffffffffu, accz, 1);
            accz += __shfl_xor_sync(0xffffffffu, accz, 2);
            char* qdst = smx + qs_off + (uint32_t)row * PHB + qtr * 32;
            *(uint4*)qdst        = make_uint4(h[0], h[1], h[2], h[3]);
            *(uint4*)(qdst + 16) = make_uint4(h[4], h[5], h[6], h[7]);
            if (qtr == 0) zs[row] = 1.f / (accz + 1e-6f);
        }
        // prefetch Q(t+1) BEFORE the barrier (qv regs dead after staging)
        if (t + 1 < NT) {
            const float* qn = qbase + (size_t)TLQ * (t + 1) * (NH * DD);
            #pragma unroll
            for (int i = 0; i < 4; i++) qv[i] = *(const float4*)(qn + i * 4);
        }
        if (t == 0) CP_WAIT(0);
        __syncthreads();

        float acc[4][4];
        #pragma unroll
        for (int i = 0; i < 4; i++)
            #pragma unroll
            for (int j = 0; j < 4; j++) acc[i][j] = 0.f;

        const uint32_t abase = smb + qs_off + a_row_bytes;
        #pragma unroll
        for (int kk = 0; kk < 4; kk++) {
            uint32_t a0, a1, a2, a3;
            LDSM_X4(a0, a1, a2, a3, abase + (uint32_t)(kk * 16 + selc * 8) * 2);
            #pragma unroll
            for (int ntp = 0; ntp < 2; ntp++) {
                uint32_t b0, b1, b2, b3;
                LDSM_X4T(b0, b1, b2, b3,
                         b_base + (uint32_t)(kk * 16) * PHB + (uint32_t)(ntp * 16) * 2);
                mma16(acc[ntp * 2],     a0, a1, a2, a3, b0, b1);
                mma16(acc[ntp * 2 + 1], a0, a1, a2, a3, b2, b3);
            }
        }

        const float z0 = zs[lw + gid];
        const float z1 = zs[lw + gid + 8];
        float* dst = O + ((size_t)pair * LL + lbase + t * TLQ + lw + gid) * DD;
        #pragma unroll
        for (int nt = 0; nt < 4; nt++) {
            const int m = m0w + nt * 8 + 2 * tig;
            *(float2*)(dst + m)          = make_float2(acc[nt][0] * z0, acc[nt][1] * z0);
            *(float2*)(dst + 8 * DD + m) = make_float2(acc[nt][2] * z1, acc[nt][3] * z1);
        }
    }
}

// ---------------- launch ----------------
extern "C" void kernel_launch(void* const* d_in, const int* in_sizes, int n_in,
                              void* d_out, int out_size) {
    const float* Q = (const float*)d_in[0];
    const float* K = (const float*)d_in[1];
    const float* V = (const float*)d_in[2];
    float* O = (float*)d_out;

    cudaFuncSetAttribute(kv_kernel,  cudaFuncAttributeMaxDynamicSharedMemorySize, K1_SMEM);
    cudaFuncSetAttribute(out_kernel, cudaFuncAttributeMaxDynamicSharedMemorySize, K2_SMEM);

    kv_kernel<<<dim3(SPL, NPAIR), 256, K1_SMEM>>>(K, V);
    out_kernel<<<dim3(LL / (TLQ * NT), NPAIR), 256, K2_SMEM>>>(Q, O);
}

// round 15
// speedup vs baseline: 1.0533x; 1.0533x over previous
#include <cuda_runtime.h>
#include <cuda_fp16.h>
#include <cstdint>

// LinearAttention n=4, L=8192, h=8, d=m=64 — f16 mma.sync m16n8k16 + ldmatrix.
// Both GEMMs use cp.async->smem operand delivery (register-free staging).
// out[pair,l,m] = z_l * sum_d phiQ[l,d] * KV[d,m]
// KV[d,m] = sum_s phiK[s,d] V[s,m];  z_l = 1/(phiQ[l,:]·ksum + 1e-6)

#define NB 4
#define LL 8192
#define NH 8
#define DD 64
#define NPAIR 32
#define SPL 32
#define CHUNK (LL / SPL)       // 256
#define ROWS 32
#define NRND (CHUNK / ROWS)    // 8
#define TLQ 64
#define NT  4
#define PH  72                 // f16 pitch in halves (144 B)
#define PHB (PH * 2)
#define RPF 68                 // raw fp32 pitch in floats (272 B)

// kv smem layout (dynamic) — R13-proven
#define KRAW_OFF 0
#define VRAW_OFF (2 * ROWS * RPF * 4)                  // 17408
#define KS_OFF   (VRAW_OFF + 2 * ROWS * RPF * 4)       // 34816
#define VS_OFF   (KS_OFF + 2 * ROWS * PHB)             // 44032
#define KSUM_OFF (VS_OFF + 2 * ROWS * PHB)             // 53248
#define K1_SMEM  (KSUM_OFF + DD * 4)                   // 53504
#define SBUF     (ROWS * PHB)                          // 4608

// out smem layout (dynamic)
#define QRAW_OFF 0                                      // TLQ x RPF fp32 = 17408
#define QS_OFF   (TLQ * RPF * 4)                        // 17408
#define KVS_OFF  (QS_OFF + 2 * TLQ * PHB)               // 35840
#define ZS_OFF   (KVS_OFF + DD * PHB)                   // 45056
#define K2_SMEM  (ZS_OFF + 2 * TLQ * 4)                 // 45568
#define QSBUF    (TLQ * PHB)                            // 9216

__device__ float  g_kv_part[SPL * NPAIR * DD * DD];
__device__ float  g_ksum_part[SPL * NPAIR * DD];
__device__ __half g_kvh[NPAIR * DD * DD];
__device__ float  g_ksum[NPAIR * DD];

// ---------------- helpers ----------------
__device__ __forceinline__ uint32_t s2u(const void* p) {
    uint32_t a;
    asm("{ .reg .u64 t; cvta.to.shared.u64 t, %1; cvt.u32.u64 %0, t; }" : "=r"(a) : "l"(p));
    return a;
}
__device__ __forceinline__ float phi(float x) {
    x *= 0.35355339059327378f;            // 64^-0.25
    return x > 0.f ? x + 1.f : __expf(x);
}
__device__ __forceinline__ uint32_t packh2(float lo, float hi) {
    __half2 h = __floats2half2_rn(lo, hi);
    return *reinterpret_cast<uint32_t*>(&h);
}
__device__ __forceinline__ void mma16(float c[4], uint32_t a0, uint32_t a1,
                                      uint32_t a2, uint32_t a3,
                                      uint32_t b0, uint32_t b1) {
    asm volatile(
        "mma.sync.aligned.m16n8k16.row.col.f32.f16.f16.f32 "
        "{%0,%1,%2,%3}, {%4,%5,%6,%7}, {%8,%9}, {%0,%1,%2,%3};"
        : "+f"(c[0]), "+f"(c[1]), "+f"(c[2]), "+f"(c[3])
        : "r"(a0), "r"(a1), "r"(a2), "r"(a3), "r"(b0), "r"(b1));
}
#define LDSM_X4(r0, r1, r2, r3, addr) \
    asm volatile("ldmatrix.sync.aligned.m8n8.x4.shared.b16 {%0,%1,%2,%3}, [%4];" \
                 : "=r"(r0), "=r"(r1), "=r"(r2), "=r"(r3) : "r"(addr))
#define LDSM_X4T(r0, r1, r2, r3, addr) \
    asm volatile("ldmatrix.sync.aligned.m8n8.x4.trans.shared.b16 {%0,%1,%2,%3}, [%4];" \
                 : "=r"(r0), "=r"(r1), "=r"(r2), "=r"(r3) : "r"(addr))
__device__ __forceinline__ void cp16(uint32_t dst, const void* src) {
    asm volatile("cp.async.cg.shared.global [%0], [%1], 16;"
                 :: "r"(dst), "l"(src) : "memory");
}
#define CP_COMMIT() asm volatile("cp.async.commit_group;" ::: "memory")
#define CP_WAIT(N)  asm volatile("cp.async.wait_group %0;" :: "n"(N) : "memory")

// ---------------- kernel 1: KV partials (R13-proven, unchanged) ----------------
__global__ __launch_bounds__(256)
void kv_kernel(const float* __restrict__ K, const float* __restrict__ V) {
    extern __shared__ char sm1[];
    const uint32_t smb = s2u(sm1);
    float* ksum_s = (float*)(sm1 + KSUM_OFF);

    const int tid = threadIdx.x, warp = tid >> 5, lane = tid & 31;
    const int gid = lane >> 2, tig = lane & 3;
    const int pair = blockIdx.y, b = pair >> 3, hh = pair & 7;
    const int split = blockIdx.x;
    const int wd = warp & 3, wm = warp >> 2;
    const int d0 = wd * 16, m0 = wm * 32;

    const size_t rstr = (size_t)NH * DD;
    const int lrow = tid >> 3, lcol = (tid & 7) * 8;
    const float* Kp = K + ((size_t)b * LL + split * CHUNK + lrow) * rstr + hh * DD + lcol;
    const float* Vp = V + ((size_t)b * LL + split * CHUNK + lrow) * rstr + hh * DD + lcol;

    const uint32_t krd = smb + KRAW_OFF + ((uint32_t)lrow * RPF + lcol) * 4;
    const uint32_t vrd = smb + VRAW_OFF + ((uint32_t)lrow * RPF + lcol) * 4;
    const uint32_t rawB = ROWS * RPF * 4;
    const uint32_t ksd = smb + KS_OFF + (uint32_t)lrow * PHB + lcol * 2;
    const uint32_t vsd = smb + VS_OFF + (uint32_t)lrow * PHB + lcol * 2;

    if (tid < DD) ksum_s[tid] = 0.f;

    float acc[4][4];
    #pragma unroll
    for (int i = 0; i < 4; i++)
        #pragma unroll
        for (int j = 0; j < 4; j++) acc[i][j] = 0.f;
    float ks[8];
    #pragma unroll
    for (int j = 0; j < 8; j++) ks[j] = 0.f;

    const int lr8  = lane & 7;
    const int sel3 = (lane >> 3) & 1;
    const int sel4 = (lane >> 4) & 1;
    const uint32_t a_addr0 = smb + KS_OFF + (uint32_t)(lr8 + sel4 * 8) * PHB
                                          + (uint32_t)(d0 + sel3 * 8) * 2;
    const uint32_t b_addr0 = smb + VS_OFF + (uint32_t)(lr8 + sel3 * 8) * PHB
                                          + (uint32_t)(m0 + sel4 * 8) * 2;

    cp16(krd, Kp); cp16(krd + 16, Kp + 4);
    cp16(vrd, Vp); cp16(vrd + 16, Vp + 4);
    CP_COMMIT();

    #pragma unroll
    for (int r = 0; r < NRND; r++) {
        const int buf = r & 1;
        if (r + 1 < NRND) {
            const size_t go = (size_t)(r + 1) * ROWS * rstr;
            const uint32_t so = (uint32_t)((r + 1) & 1) * rawB;
            cp16(krd + so, Kp + go); cp16(krd + so + 16, Kp + go + 4);
            cp16(vrd + so, Vp + go); cp16(vrd + so + 16, Vp + go + 4);
            CP_COMMIT();
            CP_WAIT(1);
        } else {
            CP_WAIT(0);
        }
        {
            const char* krp = sm1 + KRAW_OFF + buf * rawB + ((uint32_t)lrow * RPF + lcol) * 4;
            const char* vrp = sm1 + VRAW_OFF + buf * rawB + ((uint32_t)lrow * RPF + lcol) * 4;
            float4 ka = *(const float4*)krp;
            float4 kb = *(const float4*)(krp + 16);
            float4 va = *(const float4*)vrp;
            float4 vb = *(const float4*)(vrp + 16);
            float p[8];
            p[0] = phi(ka.x); p[1] = phi(ka.y); p[2] = phi(ka.z); p[3] = phi(ka.w);
            p[4] = phi(kb.x); p[5] = phi(kb.y); p[6] = phi(kb.z); p[7] = phi(kb.w);
            #pragma unroll
            for (int j = 0; j < 8; j++) ks[j] += p[j];
            uint4 hk = make_uint4(packh2(p[0], p[1]), packh2(p[2], p[3]),
                                  packh2(p[4], p[5]), packh2(p[6], p[7]));
            uint4 hv = make_uint4(packh2(va.x, va.y), packh2(va.z, va.w),
                                  packh2(vb.x, vb.y), packh2(vb.z, vb.w));
            asm volatile("st.shared.v4.b32 [%0], {%1,%2,%3,%4};"
                         :: "r"(ksd + buf * SBUF), "r"(hk.x), "r"(hk.y), "r"(hk.z), "r"(hk.w));
            asm volatile("st.shared.v4.b32 [%0], {%1,%2,%3,%4};"
                         :: "r"(vsd + buf * SBUF), "r"(hv.x), "r"(hv.y), "r"(hv.z), "r"(hv.w));
        }
        __syncthreads();

        const uint32_t aB = a_addr0 + buf * SBUF;
        const uint32_t bB = b_addr0 + buf * SBUF;
        #pragma unroll
        for (int kk = 0; kk < 2; kk++) {
            uint32_t a0, a1, a2, a3;
            LDSM_X4T(a0, a1, a2, a3, aB + (uint32_t)(kk * 16) * PHB);
            #pragma unroll
            for (int ntp = 0; ntp < 2; ntp++) {
                uint32_t b0, b1, b2, b3;
                LDSM_X4T(b0, b1, b2, b3,
                         bB + (uint32_t)(kk * 16) * PHB + (uint32_t)(ntp * 16) * 2);
                mma16(acc[ntp * 2],     a0, a1, a2, a3, b0, b1);
                mma16(acc[ntp * 2 + 1], a0, a1, a2, a3, b2, b3);
            }
        }
    }

    float* dst = g_kv_part + ((size_t)split * NPAIR + pair) * DD * DD;
    const int dlo = d0 + gid;
    #pragma unroll
    for (int nt = 0; nt < 4; nt++) {
        const int m = m0 + nt * 8 + 2 * tig;
        *(float2*)(dst + dlo * DD + m)       = make_float2(acc[nt][0], acc[nt][1]);
        *(float2*)(dst + (dlo + 8) * DD + m) = make_float2(acc[nt][2], acc[nt][3]);
    }
    #pragma unroll
    for (int j = 0; j < 8; j++) {
        ks[j] += __shfl_xor_sync(0xffffffffu, ks[j], 8);
        ks[j] += __shfl_xor_sync(0xffffffffu, ks[j], 16);
    }
    __syncthreads();
    if (lane < 8) {
        #pragma unroll
        for (int j = 0; j < 8; j++)
            atomicAdd(&ksum_s[lane * 8 + j], ks[j]);
    }
    __syncthreads();
    if (tid < DD)
        g_ksum_part[((size_t)split * NPAIR + pair) * DD + tid] = ksum_s[tid];
}

// ---------------- reduce partials (KV -> f16, ksum -> fp32) ----------------
__global__ void reduce_kernel() {
    const int i = blockIdx.x * blockDim.x + threadIdx.x;
    if (i < NPAIR * DD * DD) {
        float s = 0.f;
        #pragma unroll
        for (int p = 0; p < SPL; p++) s += g_kv_part[(size_t)p * NPAIR * DD * DD + i];
        g_kvh[i] = __float2half_rn(s);
    } else {
        const int j = i - NPAIR * DD * DD;
        if (j < NPAIR * DD) {
            float s = 0.f;
            #pragma unroll
            for (int p = 0; p < SPL; p++) s += g_ksum_part[p * NPAIR * DD + j];
            g_ksum[j] = s;
        }
    }
}

// ---------------- kernel 2: output GEMM (cp.async Q delivery, 5 CTAs/SM) ----
__global__ __launch_bounds__(256, 5)
void out_kernel(const float* __restrict__ Q, float* __restrict__ O) {
    extern __shared__ char smx[];
    const uint32_t smb = s2u(smx);
    float* zsb = (float*)(smx + ZS_OFF);

    const int tid = threadIdx.x, warp = tid >> 5, lane = tid & 31;
    const int gid = lane >> 2, tig = lane & 3;
    const int pair = blockIdx.y, b = pair >> 3, hh = pair & 7;
    const int lbase = blockIdx.x * (TLQ * NT);

    // KV tile (f16) via cp.async (group committed first)
    {
        const int krow = tid >> 2, kck = tid & 3;
        const __half* src = g_kvh + (size_t)pair * DD * DD + krow * DD + kck * 16;
        const uint32_t dst = smb + KVS_OFF + (uint32_t)krow * PHB + kck * 32;
        cp16(dst, src); cp16(dst + 16, src + 8);
    }
    CP_COMMIT();

    // per-thread q mapping: 4 threads per row, 16 d each; thread copies and
    // reads back ONLY its own quarter-row -> no barrier between wait and LDS.
    const int row = tid >> 2, qtr = tid & 3;
    const float* ksg = g_ksum + pair * DD + qtr * 16;
    float4 k4[4];
    #pragma unroll
    for (int i = 0; i < 4; i++) k4[i] = __ldg((const float4*)(ksg + i * 4));

    const float* qbase = Q + ((size_t)b * LL + lbase + row) * (NH * DD)
                           + (size_t)hh * DD + qtr * 16;
    const uint32_t qraw = smb + QRAW_OFF + ((uint32_t)row * RPF + qtr * 16) * 4;
    const char*    qrawc = smx + QRAW_OFF + ((uint32_t)row * RPF + qtr * 16) * 4;

    // prologue: cp.async Q raw tile 0
    cp16(qraw, qbase);           cp16(qraw + 16, qbase + 4);
    cp16(qraw + 32, qbase + 8);  cp16(qraw + 48, qbase + 12);
    CP_COMMIT();

    const int lw = (warp & 3) * 16;
    const int m0w = (warp >> 2) * 32;

    const int lr8  = lane & 7;
    const int seld = (lane >> 3) & 1;
    const int selc = (lane >> 4) & 1;
    const uint32_t a_row_bytes = (uint32_t)(lw + lr8 + seld * 8) * PHB;
    const uint32_t b_base = smb + KVS_OFF
                          + (uint32_t)(lr8 + seld * 8) * PHB
                          + (uint32_t)(m0w + selc * 8) * 2;

    #pragma unroll
    for (int t = 0; t < NT; t++) {
        const int buf = t & 1;
        const uint32_t qs_off = QS_OFF + (uint32_t)buf * QSBUF;
        float* zs = zsb + buf * TLQ;

        CP_WAIT(0);   // own raw(t) copies done (t=0: KV too, made visible by the sync below)

        // stage: LDS own raw -> phi + fp32 z-dot -> f16 STS qs[buf]
        {
            float4 q0 = *(const float4*)qrawc;
            float4 q1 = *(const float4*)(qrawc + 16);
            float4 q2 = *(const float4*)(qrawc + 32);
            float4 q3 = *(const float4*)(qrawc + 48);
            float p[16];
            p[0]=phi(q0.x); p[1]=phi(q0.y); p[2]=phi(q0.z); p[3]=phi(q0.w);
            p[4]=phi(q1.x); p[5]=phi(q1.y); p[6]=phi(q1.z); p[7]=phi(q1.w);
            p[8]=phi(q2.x); p[9]=phi(q2.y); p[10]=phi(q2.z); p[11]=phi(q2.w);
            p[12]=phi(q3.x); p[13]=phi(q3.y); p[14]=phi(q3.z); p[15]=phi(q3.w);
            float accz = 0.f;
            #pragma unroll
            for (int i = 0; i < 4; i++) {
                accz += p[i*4+0] * ((const float*)&k4[i])[0]
                      + p[i*4+1] * ((const float*)&k4[i])[1]
                      + p[i*4+2] * ((const float*)&k4[i])[2]
                      + p[i*4+3] * ((const float*)&k4[i])[3];
            }
            accz += __shfl_xor_sync(0xffffffffu, accz, 1);
            accz += __shfl_xor_sync(0xffffffffu, accz, 2);
            uint4 h0 = make_uint4(packh2(p[0],p[1]), packh2(p[2],p[3]),
                                  packh2(p[4],p[5]), packh2(p[6],p[7]));
            uint4 h1 = make_uint4(packh2(p[8],p[9]), packh2(p[10],p[11]),
                                  packh2(p[12],p[13]), packh2(p[14],p[15]));
            const uint32_t qdst = smb + qs_off + (uint32_t)row * PHB + qtr * 32;
            asm volatile("st.shared.v4.b32 [%0], {%1,%2,%3,%4};"
                         :: "r"(qdst), "r"(h0.x), "r"(h0.y), "r"(h0.z), "r"(h0.w));
            asm volatile("st.shared.v4.b32 [%0], {%1,%2,%3,%4};"
                         :: "r"(qdst + 16), "r"(h1.x), "r"(h1.y), "r"(h1.z), "r"(h1.w));
            if (qtr == 0) zs[row] = 1.f / (accz + 1e-6f);
        }
        // issue cp.async raw(t+1) — overlaps MMA+store below; safe: this thread
        // is done reading its own raw region, and every thread only reads its own.
        if (t + 1 < NT) {
            const float* qn = qbase + (size_t)(t + 1) * TLQ * (NH * DD);
            cp16(qraw, qn);           cp16(qraw + 16, qn + 4);
            cp16(qraw + 32, qn + 8);  cp16(qraw + 48, qn + 12);
            CP_COMMIT();
        }
        __syncthreads();   // staging (and t=0: KV) visible to all

        float acc[4][4];
        #pragma unroll
        for (int i = 0; i < 4; i++)
            #pragma unroll
            for (int j = 0; j < 4; j++) acc[i][j] = 0.f;

        const uint32_t abase = smb + qs_off + a_row_bytes;
        #pragma unroll
        for (int kk = 0; kk < 4; kk++) {
            uint32_t a0, a1, a2, a3;
            LDSM_X4(a0, a1, a2, a3, abase + (uint32_t)(kk * 16 + selc * 8) * 2);
            #pragma unroll
            for (int ntp = 0; ntp < 2; ntp++) {
                uint32_t b0, b1, b2, b3;
                LDSM_X4T(b0, b1, b2, b3,
                         b_base + (uint32_t)(kk * 16) * PHB + (uint32_t)(ntp * 16) * 2);
                mma16(acc[ntp * 2],     a0, a1, a2, a3, b0, b1);
                mma16(acc[ntp * 2 + 1], a0, a1, a2, a3, b2, b3);
            }
        }

        const float z0 = zs[lw + gid];
        const float z1 = zs[lw + gid + 8];
        float* dst = O + ((size_t)pair * LL + lbase + t * TLQ + lw + gid) * DD;
        #pragma unroll
        for (int nt = 0; nt < 4; nt++) {
            const int m = m0w + nt * 8 + 2 * tig;
            *(float2*)(dst + m)          = make_float2(acc[nt][0] * z0, acc[nt][1] * z0);
            *(float2*)(dst + 8 * DD + m) = make_float2(acc[nt][2] * z1, acc[nt][3] * z1);
        }
        // next tile stages the other qs buffer; raw is single-buffered but
        // thread-private (each thread reads only what it copied).
    }
}

// ---------------- launch ----------------
extern "C" void kernel_launch(void* const* d_in, const int* in_sizes, int n_in,
                              void* d_out, int out_size) {
    const float* Q = (const float*)d_in[0];
    const float* K = (const float*)d_in[1];
    const float* V = (const float*)d_in[2];
    float* O = (float*)d_out;

    cudaFuncSetAttribute(kv_kernel,  cudaFuncAttributeMaxDynamicSharedMemorySize, K1_SMEM);
    cudaFuncSetAttribute(out_kernel, cudaFuncAttributeMaxDynamicSharedMemorySize, K2_SMEM);

    kv_kernel<<<dim3(SPL, NPAIR), 256, K1_SMEM>>>(K, V);
    reduce_kernel<<<(NPAIR * DD * DD + NPAIR * DD + 255) / 256, 256>>>();
    out_kernel<<<dim3(LL / (TLQ * NT), NPAIR), 256, K2_SMEM>>>(Q, O);
}

// round 16
// speedup vs baseline: 1.1383x; 1.0808x over previous
#include <cuda_runtime.h>
#include <cuda_fp16.h>
#include <cstdint>

// LinearAttention n=4, L=8192, h=8, d=m=64 — f16 mma.sync m16n8k16 + ldmatrix.
// kv: R13-proven cp.async operand delivery, SPL=16 (halved partial traffic).
// out: R14-proven register Q-prefetch hoisted before tile barrier.
// out[pair,l,m] = z_l * sum_d phiQ[l,d] * KV[d,m]
// KV[d,m] = sum_s phiK[s,d] V[s,m];  z_l = 1/(phiQ[l,:]·ksum + 1e-6)

#define NB 4
#define LL 8192
#define NH 8
#define DD 64
#define NPAIR 32
#define SPL 16
#define CHUNK (LL / SPL)       // 512
#define ROWS 32
#define NRND (CHUNK / ROWS)    // 16
#define TLQ 64
#define NT  4
#define PH  72                 // f16 pitch in halves (144 B)
#define PHB (PH * 2)
#define RPF 68                 // raw fp32 pitch in floats (272 B)

// kv smem layout (dynamic) — R13-proven
#define KRAW_OFF 0
#define VRAW_OFF (2 * ROWS * RPF * 4)                  // 17408
#define KS_OFF   (VRAW_OFF + 2 * ROWS * RPF * 4)       // 34816
#define VS_OFF   (KS_OFF + 2 * ROWS * PHB)             // 44032
#define KSUM_OFF (VS_OFF + 2 * ROWS * PHB)             // 53248
#define K1_SMEM  (KSUM_OFF + DD * 4)                   // 53504
#define SBUF     (ROWS * PHB)                          // 4608

__device__ float  g_kv_part[SPL * NPAIR * DD * DD];    // 8 MB
__device__ float  g_ksum_part[SPL * NPAIR * DD];
__device__ __half g_kvh[NPAIR * DD * DD];
__device__ float  g_ksum[NPAIR * DD];

// ---------------- helpers ----------------
__device__ __forceinline__ uint32_t s2u(const void* p) {
    uint32_t a;
    asm("{ .reg .u64 t; cvta.to.shared.u64 t, %1; cvt.u32.u64 %0, t; }" : "=r"(a) : "l"(p));
    return a;
}
__device__ __forceinline__ float phi(float x) {
    x *= 0.35355339059327378f;            // 64^-0.25
    return x > 0.f ? x + 1.f : __expf(x);
}
__device__ __forceinline__ uint32_t packh2(float lo, float hi) {
    __half2 h = __floats2half2_rn(lo, hi);
    return *reinterpret_cast<uint32_t*>(&h);
}
__device__ __forceinline__ void mma16(float c[4], uint32_t a0, uint32_t a1,
                                      uint32_t a2, uint32_t a3,
                                      uint32_t b0, uint32_t b1) {
    asm volatile(
        "mma.sync.aligned.m16n8k16.row.col.f32.f16.f16.f32 "
        "{%0,%1,%2,%3}, {%4,%5,%6,%7}, {%8,%9}, {%0,%1,%2,%3};"
        : "+f"(c[0]), "+f"(c[1]), "+f"(c[2]), "+f"(c[3])
        : "r"(a0), "r"(a1), "r"(a2), "r"(a3), "r"(b0), "r"(b1));
}
#define LDSM_X4(r0, r1, r2, r3, addr) \
    asm volatile("ldmatrix.sync.aligned.m8n8.x4.shared.b16 {%0,%1,%2,%3}, [%4];" \
                 : "=r"(r0), "=r"(r1), "=r"(r2), "=r"(r3) : "r"(addr))
#define LDSM_X4T(r0, r1, r2, r3, addr) \
    asm volatile("ldmatrix.sync.aligned.m8n8.x4.trans.shared.b16 {%0,%1,%2,%3}, [%4];" \
                 : "=r"(r0), "=r"(r1), "=r"(r2), "=r"(r3) : "r"(addr))
__device__ __forceinline__ void cp16(uint32_t dst, const void* src) {
    asm volatile("cp.async.cg.shared.global [%0], [%1], 16;"
                 :: "r"(dst), "l"(src) : "memory");
}
#define CP_COMMIT() asm volatile("cp.async.commit_group;" ::: "memory")
#define CP_WAIT(N)  asm volatile("cp.async.wait_group %0;" :: "n"(N) : "memory")

// ---------------- kernel 1: KV partials (R13 body, SPL=16) ----------------
__global__ __launch_bounds__(256)
void kv_kernel(const float* __restrict__ K, const float* __restrict__ V) {
    extern __shared__ char sm1[];
    const uint32_t smb = s2u(sm1);
    float* ksum_s = (float*)(sm1 + KSUM_OFF);

    const int tid = threadIdx.x, warp = tid >> 5, lane = tid & 31;
    const int gid = lane >> 2, tig = lane & 3;
    const int pair = blockIdx.y, b = pair >> 3, hh = pair & 7;
    const int split = blockIdx.x;
    const int wd = warp & 3, wm = warp >> 2;
    const int d0 = wd * 16, m0 = wm * 32;

    const size_t rstr = (size_t)NH * DD;
    const int lrow = tid >> 3, lcol = (tid & 7) * 8;
    const float* Kp = K + ((size_t)b * LL + split * CHUNK + lrow) * rstr + hh * DD + lcol;
    const float* Vp = V + ((size_t)b * LL + split * CHUNK + lrow) * rstr + hh * DD + lcol;

    const uint32_t krd = smb + KRAW_OFF + ((uint32_t)lrow * RPF + lcol) * 4;
    const uint32_t vrd = smb + VRAW_OFF + ((uint32_t)lrow * RPF + lcol) * 4;
    const uint32_t rawB = ROWS * RPF * 4;
    const uint32_t ksd = smb + KS_OFF + (uint32_t)lrow * PHB + lcol * 2;
    const uint32_t vsd = smb + VS_OFF + (uint32_t)lrow * PHB + lcol * 2;

    if (tid < DD) ksum_s[tid] = 0.f;

    float acc[4][4];
    #pragma unroll
    for (int i = 0; i < 4; i++)
        #pragma unroll
        for (int j = 0; j < 4; j++) acc[i][j] = 0.f;
    float ks[8];
    #pragma unroll
    for (int j = 0; j < 8; j++) ks[j] = 0.f;

    const int lr8  = lane & 7;
    const int sel3 = (lane >> 3) & 1;
    const int sel4 = (lane >> 4) & 1;
    const uint32_t a_addr0 = smb + KS_OFF + (uint32_t)(lr8 + sel4 * 8) * PHB
                                          + (uint32_t)(d0 + sel3 * 8) * 2;
    const uint32_t b_addr0 = smb + VS_OFF + (uint32_t)(lr8 + sel3 * 8) * PHB
                                          + (uint32_t)(m0 + sel4 * 8) * 2;

    cp16(krd, Kp); cp16(krd + 16, Kp + 4);
    cp16(vrd, Vp); cp16(vrd + 16, Vp + 4);
    CP_COMMIT();

    #pragma unroll 2
    for (int r = 0; r < NRND; r++) {
        const int buf = r & 1;
        if (r + 1 < NRND) {
            const size_t go = (size_t)(r + 1) * ROWS * rstr;
            const uint32_t so = (uint32_t)((r + 1) & 1) * rawB;
            cp16(krd + so, Kp + go); cp16(krd + so + 16, Kp + go + 4);
            cp16(vrd + so, Vp + go); cp16(vrd + so + 16, Vp + go + 4);
            CP_COMMIT();
            CP_WAIT(1);
        } else {
            CP_WAIT(0);
        }
        {
            const char* krp = sm1 + KRAW_OFF + buf * rawB + ((uint32_t)lrow * RPF + lcol) * 4;
            const char* vrp = sm1 + VRAW_OFF + buf * rawB + ((uint32_t)lrow * RPF + lcol) * 4;
            float4 ka = *(const float4*)krp;
            float4 kb = *(const float4*)(krp + 16);
            float4 va = *(const float4*)vrp;
            float4 vb = *(const float4*)(vrp + 16);
            float p[8];
            p[0] = phi(ka.x); p[1] = phi(ka.y); p[2] = phi(ka.z); p[3] = phi(ka.w);
            p[4] = phi(kb.x); p[5] = phi(kb.y); p[6] = phi(kb.z); p[7] = phi(kb.w);
            #pragma unroll
            for (int j = 0; j < 8; j++) ks[j] += p[j];
            uint4 hk = make_uint4(packh2(p[0], p[1]), packh2(p[2], p[3]),
                                  packh2(p[4], p[5]), packh2(p[6], p[7]));
            uint4 hv = make_uint4(packh2(va.x, va.y), packh2(va.z, va.w),
                                  packh2(vb.x, vb.y), packh2(vb.z, vb.w));
            asm volatile("st.shared.v4.b32 [%0], {%1,%2,%3,%4};"
                         :: "r"(ksd + buf * SBUF), "r"(hk.x), "r"(hk.y), "r"(hk.z), "r"(hk.w));
            asm volatile("st.shared.v4.b32 [%0], {%1,%2,%3,%4};"
                         :: "r"(vsd + buf * SBUF), "r"(hv.x), "r"(hv.y), "r"(hv.z), "r"(hv.w));
        }
        __syncthreads();

        const uint32_t aB = a_addr0 + buf * SBUF;
        const uint32_t bB = b_addr0 + buf * SBUF;
        #pragma unroll
        for (int kk = 0; kk < 2; kk++) {
            uint32_t a0, a1, a2, a3;
            LDSM_X4T(a0, a1, a2, a3, aB + (uint32_t)(kk * 16) * PHB);
            #pragma unroll
            for (int ntp = 0; ntp < 2; ntp++) {
                uint32_t b0, b1, b2, b3;
                LDSM_X4T(b0, b1, b2, b3,
                         bB + (uint32_t)(kk * 16) * PHB + (uint32_t)(ntp * 16) * 2);
                mma16(acc[ntp * 2],     a0, a1, a2, a3, b0, b1);
                mma16(acc[ntp * 2 + 1], a0, a1, a2, a3, b2, b3);
            }
        }
    }

    float* dst = g_kv_part + ((size_t)split * NPAIR + pair) * DD * DD;
    const int dlo = d0 + gid;
    #pragma unroll
    for (int nt = 0; nt < 4; nt++) {
        const int m = m0 + nt * 8 + 2 * tig;
        *(float2*)(dst + dlo * DD + m)       = make_float2(acc[nt][0], acc[nt][1]);
        *(float2*)(dst + (dlo + 8) * DD + m) = make_float2(acc[nt][2], acc[nt][3]);
    }
    #pragma unroll
    for (int j = 0; j < 8; j++) {
        ks[j] += __shfl_xor_sync(0xffffffffu, ks[j], 8);
        ks[j] += __shfl_xor_sync(0xffffffffu, ks[j], 16);
    }
    __syncthreads();
    if (lane < 8) {
        #pragma unroll
        for (int j = 0; j < 8; j++)
            atomicAdd(&ksum_s[lane * 8 + j], ks[j]);
    }
    __syncthreads();
    if (tid < DD)
        g_ksum_part[((size_t)split * NPAIR + pair) * DD + tid] = ksum_s[tid];
}

// ---------------- reduce partials (KV -> f16, ksum -> fp32) ----------------
__global__ void reduce_kernel() {
    const int i = blockIdx.x * blockDim.x + threadIdx.x;
    if (i < NPAIR * DD * DD) {
        float s = 0.f;
        #pragma unroll
        for (int p = 0; p < SPL; p++) s += g_kv_part[(size_t)p * NPAIR * DD * DD + i];
        g_kvh[i] = __float2half_rn(s);
    } else {
        const int j = i - NPAIR * DD * DD;
        if (j < NPAIR * DD) {
            float s = 0.f;
            #pragma unroll
            for (int p = 0; p < SPL; p++) s += g_ksum_part[p * NPAIR * DD + j];
            g_ksum[j] = s;
        }
    }
}

// ---------------- kernel 2: output GEMM (R14-proven: prefetch before barrier) --
#define QS_BYTES  (2 * TLQ * PH * 2)
#define KVS_BYTES (DD * PH * 2)
#define K2_SMEM   (QS_BYTES + KVS_BYTES + 2 * TLQ * 4)

__global__ __launch_bounds__(256)
void out_kernel(const float* __restrict__ Q, float* __restrict__ O) {
    extern __shared__ char smx[];
    const uint32_t smb = s2u(smx);
    float* zsb = (float*)(smx + QS_BYTES + KVS_BYTES);

    const int tid = threadIdx.x, warp = tid >> 5, lane = tid & 31;
    const int gid = lane >> 2, tig = lane & 3;
    const int pair = blockIdx.y, b = pair >> 3, hh = pair & 7;
    const int lbase = blockIdx.x * (TLQ * NT);

    {
        const int krow = tid >> 2, kck = tid & 3;
        const __half* src = g_kvh + (size_t)pair * DD * DD + krow * DD + kck * 16;
        const uint32_t dst = smb + QS_BYTES + (uint32_t)krow * PHB + kck * 32;
        cp16(dst, src); cp16(dst + 16, src + 8);
    }
    CP_COMMIT();

    const int row = tid >> 2, qtr = tid & 3;
    const float* ksg = g_ksum + pair * DD + qtr * 16;
    float4 k4[4];
    #pragma unroll
    for (int i = 0; i < 4; i++) k4[i] = __ldg((const float4*)(ksg + i * 4));

    const float* qbase = Q + ((size_t)b * LL + lbase + row) * (NH * DD)
                           + (size_t)hh * DD + qtr * 16;
    float4 qv[4];
    #pragma unroll
    for (int i = 0; i < 4; i++) qv[i] = *(const float4*)(qbase + i * 4);

    const int lw = (warp & 3) * 16;
    const int m0w = (warp >> 2) * 32;

    const int lr8  = lane & 7;
    const int seld = (lane >> 3) & 1;
    const int selc = (lane >> 4) & 1;
    const uint32_t a_row_bytes = (uint32_t)(lw + lr8 + seld * 8) * PHB;
    const uint32_t b_base = smb + QS_BYTES
                          + (uint32_t)(lr8 + seld * 8) * PHB
                          + (uint32_t)(m0w + selc * 8) * 2;

    #pragma unroll
    for (int t = 0; t < NT; t++) {
        const int buf = t & 1;
        const uint32_t qs_off = (uint32_t)buf * (TLQ * PHB);
        float* zs = zsb + buf * TLQ;

        {
            float accz = 0.f;
            uint32_t h[8];
            #pragma unroll
            for (int i = 0; i < 4; i++) {
                float4 q4 = qv[i];
                q4.x = phi(q4.x); q4.y = phi(q4.y); q4.z = phi(q4.z); q4.w = phi(q4.w);
                accz += q4.x * k4[i].x + q4.y * k4[i].y
                      + q4.z * k4[i].z + q4.w * k4[i].w;
                h[i * 2]     = packh2(q4.x, q4.y);
                h[i * 2 + 1] = packh2(q4.z, q4.w);
            }
            accz += __shfl_xor_sync(0xffffffffu, accz, 1);
            accz += __shfl_xor_sync(0xffffffffu, accz, 2);
            char* qdst = smx + qs_off + (uint32_t)row * PHB + qtr * 32;
            *(uint4*)qdst        = make_uint4(h[0], h[1], h[2], h[3]);
            *(uint4*)(qdst + 16) = make_uint4(h[4], h[5], h[6], h[7]);
            if (qtr == 0) zs[row] = 1.f / (accz + 1e-6f);
        }
        // prefetch Q(t+1) BEFORE the barrier (qv regs dead after staging)
        if (t + 1 < NT) {
            const float* qn = qbase + (size_t)TLQ * (t + 1) * (NH * DD);
            #pragma unroll
            for (int i = 0; i < 4; i++) qv[i] = *(const float4*)(qn + i * 4);
        }
        if (t == 0) CP_WAIT(0);
        __syncthreads();

        float acc[4][4];
        #pragma unroll
        for (int i = 0; i < 4; i++)
            #pragma unroll
            for (int j = 0; j < 4; j++) acc[i][j] = 0.f;

        const uint32_t abase = smb + qs_off + a_row_bytes;
        #pragma unroll
        for (int kk = 0; kk < 4; kk++) {
            uint32_t a0, a1, a2, a3;
            LDSM_X4(a0, a1, a2, a3, abase + (uint32_t)(kk * 16 + selc * 8) * 2);
            #pragma unroll
            for (int ntp = 0; ntp < 2; ntp++) {
                uint32_t b0, b1, b2, b3;
                LDSM_X4T(b0, b1, b2, b3,
                         b_base + (uint32_t)(kk * 16) * PHB + (uint32_t)(ntp * 16) * 2);
                mma16(acc[ntp * 2],     a0, a1, a2, a3, b0, b1);
                mma16(acc[ntp * 2 + 1], a0, a1, a2, a3, b2, b3);
            }
        }

        const float z0 = zs[lw + gid];
        const float z1 = zs[lw + gid + 8];
        float* dst = O + ((size_t)pair * LL + lbase + t * TLQ + lw + gid) * DD;
        #pragma unroll
        for (int nt = 0; nt < 4; nt++) {
            const int m = m0w + nt * 8 + 2 * tig;
            *(float2*)(dst + m)          = make_float2(acc[nt][0] * z0, acc[nt][1] * z0);
            *(float2*)(dst + 8 * DD + m) = make_float2(acc[nt][2] * z1, acc[nt][3] * z1);
        }
    }
}

// ---------------- launch ----------------
extern "C" void kernel_launch(void* const* d_in, const int* in_sizes, int n_in,
                              void* d_out, int out_size) {
    const float* Q = (const float*)d_in[0];
    const float* K = (const float*)d_in[1];
    const float* V = (const float*)d_in[2];
    float* O = (float*)d_out;

    cudaFuncSetAttribute(kv_kernel,  cudaFuncAttributeMaxDynamicSharedMemorySize, K1_SMEM);
    cudaFuncSetAttribute(out_kernel, cudaFuncAttributeMaxDynamicSharedMemorySize, K2_SMEM);

    kv_kernel<<<dim3(SPL, NPAIR), 256, K1_SMEM>>>(K, V);
    reduce_kernel<<<(NPAIR * DD * DD + NPAIR * DD + 255) / 256, 256>>>();
    out_kernel<<<dim3(LL / (TLQ * NT), NPAIR), 256, K2_SMEM>>>(Q, O);
}

// round 17
// speedup vs baseline: 1.1427x; 1.0039x over previous
#include <cuda_runtime.h>
#include <cuda_fp16.h>
#include <cstdint>

// LinearAttention n=4, L=8192, h=8, d=m=64 — f16 mma.sync m16n8k16 + ldmatrix.
// kv: R13-proven cp.async delivery (SPL=32) with f16 partial KV (halved traffic).
// out: R14/R16-proven register Q-prefetch hoisted before tile barrier.
// out[pair,l,m] = z_l * sum_d phiQ[l,d] * KV[d,m]
// KV[d,m] = sum_s phiK[s,d] V[s,m];  z_l = 1/(phiQ[l,:]·ksum + 1e-6)

#define NB 4
#define LL 8192
#define NH 8
#define DD 64
#define NPAIR 32
#define SPL 32
#define CHUNK (LL / SPL)       // 256
#define ROWS 32
#define NRND (CHUNK / ROWS)    // 8
#define TLQ 64
#define NT  4
#define PH  72                 // f16 pitch in halves (144 B)
#define PHB (PH * 2)
#define RPF 68                 // raw fp32 pitch in floats (272 B)

// kv smem layout (dynamic) — R13-proven
#define KRAW_OFF 0
#define VRAW_OFF (2 * ROWS * RPF * 4)                  // 17408
#define KS_OFF   (VRAW_OFF + 2 * ROWS * RPF * 4)       // 34816
#define VS_OFF   (KS_OFF + 2 * ROWS * PHB)             // 44032
#define KSUM_OFF (VS_OFF + 2 * ROWS * PHB)             // 53248
#define K1_SMEM  (KSUM_OFF + DD * 4)                   // 53504
#define SBUF     (ROWS * PHB)                          // 4608

__device__ __half g_kv_parth[SPL * NPAIR * DD * DD];   // 8 MB (f16 partials)
__device__ float  g_ksum_part[SPL * NPAIR * DD];
__device__ __half g_kvh[NPAIR * DD * DD];
__device__ float  g_ksum[NPAIR * DD];

// ---------------- helpers ----------------
__device__ __forceinline__ uint32_t s2u(const void* p) {
    uint32_t a;
    asm("{ .reg .u64 t; cvta.to.shared.u64 t, %1; cvt.u32.u64 %0, t; }" : "=r"(a) : "l"(p));
    return a;
}
__device__ __forceinline__ float phi(float x) {
    x *= 0.35355339059327378f;            // 64^-0.25
    return x > 0.f ? x + 1.f : __expf(x);
}
__device__ __forceinline__ uint32_t packh2(float lo, float hi) {
    __half2 h = __floats2half2_rn(lo, hi);
    return *reinterpret_cast<uint32_t*>(&h);
}
__device__ __forceinline__ void mma16(float c[4], uint32_t a0, uint32_t a1,
                                      uint32_t a2, uint32_t a3,
                                      uint32_t b0, uint32_t b1) {
    asm volatile(
        "mma.sync.aligned.m16n8k16.row.col.f32.f16.f16.f32 "
        "{%0,%1,%2,%3}, {%4,%5,%6,%7}, {%8,%9}, {%0,%1,%2,%3};"
        : "+f"(c[0]), "+f"(c[1]), "+f"(c[2]), "+f"(c[3])
        : "r"(a0), "r"(a1), "r"(a2), "r"(a3), "r"(b0), "r"(b1));
}
#define LDSM_X4(r0, r1, r2, r3, addr) \
    asm volatile("ldmatrix.sync.aligned.m8n8.x4.shared.b16 {%0,%1,%2,%3}, [%4];" \
                 : "=r"(r0), "=r"(r1), "=r"(r2), "=r"(r3) : "r"(addr))
#define LDSM_X4T(r0, r1, r2, r3, addr) \
    asm volatile("ldmatrix.sync.aligned.m8n8.x4.trans.shared.b16 {%0,%1,%2,%3}, [%4];" \
                 : "=r"(r0), "=r"(r1), "=r"(r2), "=r"(r3) : "r"(addr))
__device__ __forceinline__ void cp16(uint32_t dst, const void* src) {
    asm volatile("cp.async.cg.shared.global [%0], [%1], 16;"
                 :: "r"(dst), "l"(src) : "memory");
}
#define CP_COMMIT() asm volatile("cp.async.commit_group;" ::: "memory")
#define CP_WAIT(N)  asm volatile("cp.async.wait_group %0;" :: "n"(N) : "memory")

// ---------------- kernel 1: KV partials (R13 body, f16 partial output) ------
__global__ __launch_bounds__(256)
void kv_kernel(const float* __restrict__ K, const float* __restrict__ V) {
    extern __shared__ char sm1[];
    const uint32_t smb = s2u(sm1);
    float* ksum_s = (float*)(sm1 + KSUM_OFF);

    const int tid = threadIdx.x, warp = tid >> 5, lane = tid & 31;
    const int gid = lane >> 2, tig = lane & 3;
    const int pair = blockIdx.y, b = pair >> 3, hh = pair & 7;
    const int split = blockIdx.x;
    const int wd = warp & 3, wm = warp >> 2;
    const int d0 = wd * 16, m0 = wm * 32;

    const size_t rstr = (size_t)NH * DD;
    const int lrow = tid >> 3, lcol = (tid & 7) * 8;
    const float* Kp = K + ((size_t)b * LL + split * CHUNK + lrow) * rstr + hh * DD + lcol;
    const float* Vp = V + ((size_t)b * LL + split * CHUNK + lrow) * rstr + hh * DD + lcol;

    const uint32_t krd = smb + KRAW_OFF + ((uint32_t)lrow * RPF + lcol) * 4;
    const uint32_t vrd = smb + VRAW_OFF + ((uint32_t)lrow * RPF + lcol) * 4;
    const uint32_t rawB = ROWS * RPF * 4;
    const uint32_t ksd = smb + KS_OFF + (uint32_t)lrow * PHB + lcol * 2;
    const uint32_t vsd = smb + VS_OFF + (uint32_t)lrow * PHB + lcol * 2;

    if (tid < DD) ksum_s[tid] = 0.f;

    float acc[4][4];
    #pragma unroll
    for (int i = 0; i < 4; i++)
        #pragma unroll
        for (int j = 0; j < 4; j++) acc[i][j] = 0.f;
    float ks[8];
    #pragma unroll
    for (int j = 0; j < 8; j++) ks[j] = 0.f;

    const int lr8  = lane & 7;
    const int sel3 = (lane >> 3) & 1;
    const int sel4 = (lane >> 4) & 1;
    const uint32_t a_addr0 = smb + KS_OFF + (uint32_t)(lr8 + sel4 * 8) * PHB
                                          + (uint32_t)(d0 + sel3 * 8) * 2;
    const uint32_t b_addr0 = smb + VS_OFF + (uint32_t)(lr8 + sel3 * 8) * PHB
                                          + (uint32_t)(m0 + sel4 * 8) * 2;

    cp16(krd, Kp); cp16(krd + 16, Kp + 4);
    cp16(vrd, Vp); cp16(vrd + 16, Vp + 4);
    CP_COMMIT();

    #pragma unroll
    for (int r = 0; r < NRND; r++) {
        const int buf = r & 1;
        if (r + 1 < NRND) {
            const size_t go = (size_t)(r + 1) * ROWS * rstr;
            const uint32_t so = (uint32_t)((r + 1) & 1) * rawB;
            cp16(krd + so, Kp + go); cp16(krd + so + 16, Kp + go + 4);
            cp16(vrd + so, Vp + go); cp16(vrd + so + 16, Vp + go + 4);
            CP_COMMIT();
            CP_WAIT(1);
        } else {
            CP_WAIT(0);
        }
        {
            const char* krp = sm1 + KRAW_OFF + buf * rawB + ((uint32_t)lrow * RPF + lcol) * 4;
            const char* vrp = sm1 + VRAW_OFF + buf * rawB + ((uint32_t)lrow * RPF + lcol) * 4;
            float4 ka = *(const float4*)krp;
            float4 kb = *(const float4*)(krp + 16);
            float4 va = *(const float4*)vrp;
            float4 vb = *(const float4*)(vrp + 16);
            float p[8];
            p[0] = phi(ka.x); p[1] = phi(ka.y); p[2] = phi(ka.z); p[3] = phi(ka.w);
            p[4] = phi(kb.x); p[5] = phi(kb.y); p[6] = phi(kb.z); p[7] = phi(kb.w);
            #pragma unroll
            for (int j = 0; j < 8; j++) ks[j] += p[j];
            uint4 hk = make_uint4(packh2(p[0], p[1]), packh2(p[2], p[3]),
                                  packh2(p[4], p[5]), packh2(p[6], p[7]));
            uint4 hv = make_uint4(packh2(va.x, va.y), packh2(va.z, va.w),
                                  packh2(vb.x, vb.y), packh2(vb.z, vb.w));
            asm volatile("st.shared.v4.b32 [%0], {%1,%2,%3,%4};"
                         :: "r"(ksd + buf * SBUF), "r"(hk.x), "r"(hk.y), "r"(hk.z), "r"(hk.w));
            asm volatile("st.shared.v4.b32 [%0], {%1,%2,%3,%4};"
                         :: "r"(vsd + buf * SBUF), "r"(hv.x), "r"(hv.y), "r"(hv.z), "r"(hv.w));
        }
        __syncthreads();

        const uint32_t aB = a_addr0 + buf * SBUF;
        const uint32_t bB = b_addr0 + buf * SBUF;
        #pragma unroll
        for (int kk = 0; kk < 2; kk++) {
            uint32_t a0, a1, a2, a3;
            LDSM_X4T(a0, a1, a2, a3, aB + (uint32_t)(kk * 16) * PHB);
            #pragma unroll
            for (int ntp = 0; ntp < 2; ntp++) {
                uint32_t b0, b1, b2, b3;
                LDSM_X4T(b0, b1, b2, b3,
                         bB + (uint32_t)(kk * 16) * PHB + (uint32_t)(ntp * 16) * 2);
                mma16(acc[ntp * 2],     a0, a1, a2, a3, b0, b1);
                mma16(acc[ntp * 2 + 1], a0, a1, a2, a3, b2, b3);
            }
        }
    }

    // epilogue: f16 partial KV -> gmem (half the write traffic)
    __half* dst = g_kv_parth + ((size_t)split * NPAIR + pair) * DD * DD;
    const int dlo = d0 + gid;
    #pragma unroll
    for (int nt = 0; nt < 4; nt++) {
        const int m = m0 + nt * 8 + 2 * tig;
        *(__half2*)(dst + dlo * DD + m)       = __floats2half2_rn(acc[nt][0], acc[nt][1]);
        *(__half2*)(dst + (dlo + 8) * DD + m) = __floats2half2_rn(acc[nt][2], acc[nt][3]);
    }
    #pragma unroll
    for (int j = 0; j < 8; j++) {
        ks[j] += __shfl_xor_sync(0xffffffffu, ks[j], 8);
        ks[j] += __shfl_xor_sync(0xffffffffu, ks[j], 16);
    }
    __syncthreads();
    if (lane < 8) {
        #pragma unroll
        for (int j = 0; j < 8; j++)
            atomicAdd(&ksum_s[lane * 8 + j], ks[j]);
    }
    __syncthreads();
    if (tid < DD)
        g_ksum_part[((size_t)split * NPAIR + pair) * DD + tid] = ksum_s[tid];
}

// ---------------- reduce partials (f16 -> fp32 acc -> f16; ksum fp32) ------
#define NKV2 (NPAIR * DD * DD / 2)   // 65536 half2 elements
__global__ void reduce_kernel() {
    const int i = blockIdx.x * blockDim.x + threadIdx.x;
    if (i < NKV2) {
        float sx = 0.f, sy = 0.f;
        const __half2* src = (const __half2*)g_kv_parth;
        #pragma unroll
        for (int p = 0; p < SPL; p++) {
            const float2 v = __half22float2(src[(size_t)p * NKV2 + i]);
            sx += v.x; sy += v.y;
        }
        ((__half2*)g_kvh)[i] = __floats2half2_rn(sx, sy);
    } else {
        const int j = i - NKV2;
        if (j < NPAIR * DD) {
            float s = 0.f;
            #pragma unroll
            for (int p = 0; p < SPL; p++) s += g_ksum_part[p * NPAIR * DD + j];
            g_ksum[j] = s;
        }
    }
}

// ---------------- kernel 2: output GEMM (R14/R16-proven) --------------------
#define QS_BYTES  (2 * TLQ * PH * 2)
#define KVS_BYTES (DD * PH * 2)
#define K2_SMEM   (QS_BYTES + KVS_BYTES + 2 * TLQ * 4)

__global__ __launch_bounds__(256)
void out_kernel(const float* __restrict__ Q, float* __restrict__ O) {
    extern __shared__ char smx[];
    const uint32_t smb = s2u(smx);
    float* zsb = (float*)(smx + QS_BYTES + KVS_BYTES);

    const int tid = threadIdx.x, warp = tid >> 5, lane = tid & 31;
    const int gid = lane >> 2, tig = lane & 3;
    const int pair = blockIdx.y, b = pair >> 3, hh = pair & 7;
    const int lbase = blockIdx.x * (TLQ * NT);

    {
        const int krow = tid >> 2, kck = tid & 3;
        const __half* src = g_kvh + (size_t)pair * DD * DD + krow * DD + kck * 16;
        const uint32_t dst = smb + QS_BYTES + (uint32_t)krow * PHB + kck * 32;
        cp16(dst, src); cp16(dst + 16, src + 8);
    }
    CP_COMMIT();

    const int row = tid >> 2, qtr = tid & 3;
    const float* ksg = g_ksum + pair * DD + qtr * 16;
    float4 k4[4];
    #pragma unroll
    for (int i = 0; i < 4; i++) k4[i] = __ldg((const float4*)(ksg + i * 4));

    const float* qbase = Q + ((size_t)b * LL + lbase + row) * (NH * DD)
                           + (size_t)hh * DD + qtr * 16;
    float4 qv[4];
    #pragma unroll
    for (int i = 0; i < 4; i++) qv[i] = *(const float4*)(qbase + i * 4);

    const int lw = (warp & 3) * 16;
    const int m0w = (warp >> 2) * 32;

    const int lr8  = lane & 7;
    const int seld = (lane >> 3) & 1;
    const int selc = (lane >> 4) & 1;
    const uint32_t a_row_bytes = (uint32_t)(lw + lr8 + seld * 8) * PHB;
    const uint32_t b_base = smb + QS_BYTES
                          + (uint32_t)(lr8 + seld * 8) * PHB
                          + (uint32_t)(m0w + selc * 8) * 2;

    #pragma unroll
    for (int t = 0; t < NT; t++) {
        const int buf = t & 1;
        const uint32_t qs_off = (uint32_t)buf * (TLQ * PHB);
        float* zs = zsb + buf * TLQ;

        {
            float accz = 0.f;
            uint32_t h[8];
            #pragma unroll
            for (int i = 0; i < 4; i++) {
                float4 q4 = qv[i];
                q4.x = phi(q4.x); q4.y = phi(q4.y); q4.z = phi(q4.z); q4.w = phi(q4.w);
                accz += q4.x * k4[i].x + q4.y * k4[i].y
                      + q4.z * k4[i].z + q4.w * k4[i].w;
                h[i * 2]     = packh2(q4.x, q4.y);
                h[i * 2 + 1] = packh2(q4.z, q4.w);
            }
            accz += __shfl_xor_sync(0xffffffffu, accz, 1);
            accz += __shfl_xor_sync(0xffffffffu, accz, 2);
            char* qdst = smx + qs_off + (uint32_t)row * PHB + qtr * 32;
            *(uint4*)qdst        = make_uint4(h[0], h[1], h[2], h[3]);
            *(uint4*)(qdst + 16) = make_uint4(h[4], h[5], h[6], h[7]);
            if (qtr == 0) zs[row] = 1.f / (accz + 1e-6f);
        }
        // prefetch Q(t+1) BEFORE the barrier (qv regs dead after staging)
        if (t + 1 < NT) {
            const float* qn = qbase + (size_t)TLQ * (t + 1) * (NH * DD);
            #pragma unroll
            for (int i = 0; i < 4; i++) qv[i] = *(const float4*)(qn + i * 4);
        }
        if (t == 0) CP_WAIT(0);
        __syncthreads();

        float acc[4][4];
        #pragma unroll
        for (int i = 0; i < 4; i++)
            #pragma unroll
            for (int j = 0; j < 4; j++) acc[i][j] = 0.f;

        const uint32_t abase = smb + qs_off + a_row_bytes;
        #pragma unroll
        for (int kk = 0; kk < 4; kk++) {
            uint32_t a0, a1, a2, a3;
            LDSM_X4(a0, a1, a2, a3, abase + (uint32_t)(kk * 16 + selc * 8) * 2);
            #pragma unroll
            for (int ntp = 0; ntp < 2; ntp++) {
                uint32_t b0, b1, b2, b3;
                LDSM_X4T(b0, b1, b2, b3,
                         b_base + (uint32_t)(kk * 16) * PHB + (uint32_t)(ntp * 16) * 2);
                mma16(acc[ntp * 2],     a0, a1, a2, a3, b0, b1);
                mma16(acc[ntp * 2 + 1], a0, a1, a2, a3, b2, b3);
            }
        }

        const float z0 = zs[lw + gid];
        const float z1 = zs[lw + gid + 8];
        float* dst = O + ((size_t)pair * LL + lbase + t * TLQ + lw + gid) * DD;
        #pragma unroll
        for (int nt = 0; nt < 4; nt++) {
            const int m = m0w + nt * 8 + 2 * tig;
            *(float2*)(dst + m)          = make_float2(acc[nt][0] * z0, acc[nt][1] * z0);
            *(float2*)(dst + 8 * DD + m) = make_float2(acc[nt][2] * z1, acc[nt][3] * z1);
        }
    }
}

// ---------------- launch ----------------
extern "C" void kernel_launch(void* const* d_in, const int* in_sizes, int n_in,
                              void* d_out, int out_size) {
    const float* Q = (const float*)d_in[0];
    const float* K = (const float*)d_in[1];
    const float* V = (const float*)d_in[2];
    float* O = (float*)d_out;

    cudaFuncSetAttribute(kv_kernel,  cudaFuncAttributeMaxDynamicSharedMemorySize, K1_SMEM);
    cudaFuncSetAttribute(out_kernel, cudaFuncAttributeMaxDynamicSharedMemorySize, K2_SMEM);

    kv_kernel<<<dim3(SPL, NPAIR), 256, K1_SMEM>>>(K, V);
    reduce_kernel<<<(NKV2 + NPAIR * DD + 255) / 256, 256>>>();
    out_kernel<<<dim3(LL / (TLQ * NT), NPAIR), 256, K2_SMEM>>>(Q, O);
}